// round 6
// baseline (speedup 1.0000x reference)
#include <cuda_runtime.h>
#include <math.h>
#include <cstdint>

#define B_  4
#define N_  16384
#define C_  64
#define M_  2048
#define NS_ 32

// FPS cluster config
#define CS    16                  // CTAs per batch (nonportable cluster)
#define FT    128                 // threads per FPS CTA
#define NW    (FT / 32)           // 4 warps
#define NPC   (N_ / CS)           // 1024 points per CTA
#define PPT2  (NPC / FT)          // 8
#define PAIRS (PPT2 / 2)          // 4
#define NKEYS (CS * NW)           // 64 keys per exchange
#define XBYTES (NKEYS * 8)        // 512 bytes per buffer

typedef unsigned long long u64;

// scratch
__device__ int   g_ballidx[B_ * M_ * NS_];
__device__ float g_soa[3][B_][N_];

// ------------------------------------------------------------------
// PTX helpers
// ------------------------------------------------------------------
__device__ __forceinline__ uint32_t smem_u32(const void* p) {
    uint32_t a;
    asm("{ .reg .u64 t; cvta.to.shared.u64 t, %1; cvt.u32.u64 %0, t; }"
        : "=r"(a) : "l"(p));
    return a;
}
__device__ __forceinline__ uint32_t ctarank() {
    uint32_t r; asm("mov.u32 %0, %%cluster_ctarank;" : "=r"(r)); return r;
}
__device__ __forceinline__ uint32_t mapa_u32(uint32_t addr, uint32_t rank) {
    uint32_t r;
    asm("mapa.shared::cluster.u32 %0, %1, %2;" : "=r"(r) : "r"(addr), "r"(rank));
    return r;
}
__device__ __forceinline__ void st_rel64(uint32_t raddr, u64 v) {
    asm volatile("st.relaxed.cluster.shared::cluster.b64 [%0], %1;"
                 :: "r"(raddr), "l"(v) : "memory");
}
__device__ __forceinline__ void ld_vol_v2(u64& k0, u64& k1, uint32_t addr) {
    asm volatile("ld.volatile.shared.v2.u64 {%0,%1}, [%2];"
                 : "=l"(k0), "=l"(k1) : "r"(addr) : "memory");
}
__device__ __forceinline__ u64 pack2(float lo, float hi) {
    u64 r;
    asm("mov.b64 %0, {%1,%2};" : "=l"(r)
        : "r"(__float_as_uint(lo)), "r"(__float_as_uint(hi)));
    return r;
}
__device__ __forceinline__ u64 pack2u(uint32_t lo, uint32_t hi) {
    u64 r;
    asm("mov.b64 %0, {%1,%2};" : "=l"(r) : "r"(lo), "r"(hi));
    return r;
}
__device__ __forceinline__ void unpack2(float& lo, float& hi, u64 v) {
    uint32_t a, b;
    asm("mov.b64 {%0,%1}, %2;" : "=r"(a), "=r"(b) : "l"(v));
    lo = __uint_as_float(a); hi = __uint_as_float(b);
}
__device__ __forceinline__ u64 addx2(u64 a, u64 b) {
    u64 r; asm("add.rn.f32x2 %0, %1, %2;" : "=l"(r) : "l"(a), "l"(b)); return r;
}
__device__ __forceinline__ u64 mulx2(u64 a, u64 b) {
    u64 r; asm("mul.rn.f32x2 %0, %1, %2;" : "=l"(r) : "l"(a), "l"(b)); return r;
}
__device__ __forceinline__ u64 fmax2(u64 a, u64 b, u64 c) {
    u64 r; asm("fma.rn.f32x2 %0, %1, %2, %3;" : "=l"(r) : "l"(a), "l"(b), "l"(c));
    return r;
}

// ------------------------------------------------------------------
// FPS: one 16-CTA cluster per batch. Full xyz mirror in dynamic smem;
// per-warp winners shipped via plain relaxed DSMEM stores with the
// iteration tag embedded in the key (no mbarrier); receiver polls its
// 64 slots with volatile v2 loads, then two-stage REDUX argmax.
// Key: [63:32]=dist bits, [24:11]=0x3FFF-idx, [10:0]=iteration tag.
// ------------------------------------------------------------------
__global__ __launch_bounds__(FT, 1)
void fps_kernel(const float* __restrict__ xyz, float* __restrict__ newxyz)
{
    extern __shared__ float mir[];         // [3][N_] coordinate mirror
    float* sxF = mir;
    float* syF = mir + N_;
    float* szF = mir + 2 * N_;

    __shared__ alignas(16) u64 cand[2][NKEYS];

    const uint32_t rank = ctarank();
    const int b = blockIdx.x / CS;
    const int t = threadIdx.x;
    const int wid = t >> 5;
    const int lane = t & 31;
    const uint32_t candB = smem_u32(&cand[0][0]);

    // zero both candidate buffers (tag 0 never polled; it starts at 1)
    for (int i = t; i < 2 * NKEYS; i += FT) cand[0][i] = 0ull;

    // load full batch xyz into mirror (SoA)
    const float* base = xyz + (size_t)b * N_ * 3;
    for (int i = t; i < N_; i += FT) {
        sxF[i] = base[3 * i + 0];
        syF[i] = base[3 * i + 1];
        szF[i] = base[3 * i + 2];
    }
    __syncthreads();

    // dump this CTA's chunk to the global SoA for ballquery/mlp
    const int goff = (int)rank * NPC;
    for (int i = goff + t; i < goff + NPC; i += FT) {
        g_soa[0][b][i] = sxF[i];
        g_soa[1][b][i] = syF[i];
        g_soa[2][b][i] = szF[i];
    }

    asm volatile("barrier.cluster.arrive.aligned;" ::: "memory");
    asm volatile("barrier.cluster.wait.aligned;" ::: "memory");

    // own points packed in registers
    u64 qx2[PAIRS], qy2[PAIRS], qz2[PAIRS];
    float qd[PPT2];
#pragma unroll
    for (int j = 0; j < PAIRS; ++j) {
        int nA = goff + (2 * j) * FT + t, nB = goff + (2 * j + 1) * FT + t;
        qx2[j] = pack2(sxF[nA], sxF[nB]);
        qy2[j] = pack2(syF[nA], syF[nB]);
        qz2[j] = pack2(szF[nA], szF[nB]);
        qd[2 * j] = 1e10f; qd[2 * j + 1] = 1e10f;
    }

    // precomputed remote slot addresses (lane < CS targets CTA 'lane')
    const uint32_t myslotoff = (uint32_t)(rank * NW + wid) * 8;
    uint32_t rc0 = 0, rc1 = 0;
    if (lane < CS) {
        rc0 = mapa_u32(candB + myslotoff,                    (uint32_t)lane);
        rc1 = mapa_u32(candB + (uint32_t)XBYTES + myslotoff, (uint32_t)lane);
    }
    const uint32_t pollA = candB + (uint32_t)lane * 16;

    float px = sxF[0], py = syF[0], pz = szF[0];
    if (rank == 0 && t == 0) {
        float* o = newxyz + (size_t)b * M_ * 3;
        o[0] = px; o[1] = py; o[2] = pz;
    }

    for (int it = 1; it < M_; ++it) {
        const uint32_t s = (uint32_t)it & 1u;

        u64 npx2 = pack2(-px, -px);
        u64 npy2 = pack2(-py, -py);
        u64 npz2 = pack2(-pz, -pz);

        float n[PPT2];
#pragma unroll
        for (int j = 0; j < PAIRS; ++j) {
            u64 dx2 = addx2(qx2[j], npx2);
            u64 dy2 = addx2(qy2[j], npy2);
            u64 dz2 = addx2(qz2[j], npz2);
            u64 ss = addx2(addx2(mulx2(dx2, dx2), mulx2(dy2, dy2)),
                           mulx2(dz2, dz2));
            float d0, d1; unpack2(d0, d1, ss);
            n[2 * j]     = fminf(qd[2 * j], d0);     qd[2 * j]     = n[2 * j];
            n[2 * j + 1] = fminf(qd[2 * j + 1], d1); qd[2 * j + 1] = n[2 * j + 1];
        }

        // local value-max tree + first-matching-slot (ascending index)
        float a0 = fmaxf(n[0], n[1]), a1 = fmaxf(n[2], n[3]);
        float a2 = fmaxf(n[4], n[5]), a3 = fmaxf(n[6], n[7]);
        float vmax = fmaxf(fmaxf(a0, a1), fmaxf(a2, a3));
        int c0 = (n[0] == vmax) ? 0 : 99, c1 = (n[1] == vmax) ? 1 : 99;
        int c2 = (n[2] == vmax) ? 2 : 99, c3 = (n[3] == vmax) ? 3 : 99;
        int c4 = (n[4] == vmax) ? 4 : 99, c5 = (n[5] == vmax) ? 5 : 99;
        int c6 = (n[6] == vmax) ? 6 : 99, c7 = (n[7] == vmax) ? 7 : 99;
        int bk = min(min(min(c0, c1), min(c2, c3)),
                     min(min(c4, c5), min(c6, c7)));

        // warp-level exact argmax (d>=0 -> float bits monotonic as uint)
        unsigned vb = __float_as_uint(vmax);
        unsigned vmaxW = __reduce_max_sync(0xffffffffu, vb);
        unsigned gidx = (unsigned)goff + (unsigned)bk * FT + (unsigned)t;
        unsigned ic = (vb == vmaxW) ? gidx : 0xffffffffu;
        unsigned imin = __reduce_min_sync(0xffffffffu, ic);
        u64 key = ((u64)vmaxW << 32)
                | ((u64)(0x3FFFu - imin) << 11)
                | (u64)(unsigned)it;

        // ship this warp's winner to all CTAs (lanes 0..CS-1)
        if (lane < CS)
            st_rel64(s ? rc1 : rc0, key);

        // poll own 2 slots until all 64 keys carry this iteration's tag
        const uint32_t pa = pollA + s * (uint32_t)XBYTES;
        u64 k0, k1;
        for (;;) {
            ld_vol_v2(k0, k1, pa);
            bool ok = (((unsigned)k0 & 0x7FFu) == (unsigned)it) &&
                      (((unsigned)k1 & 0x7FFu) == (unsigned)it);
            if (__all_sync(0xffffffffu, ok)) break;
        }

        // two-stage REDUX lexicographic max over 64 keys
        unsigned h0 = (unsigned)(k0 >> 32), h1 = (unsigned)(k1 >> 32);
        unsigned vg = __reduce_max_sync(0xffffffffu, max(h0, h1));
        unsigned l0 = (h0 == vg) ? (unsigned)k0 : 0u;
        unsigned l1 = (h1 == vg) ? (unsigned)k1 : 0u;
        unsigned lg = __reduce_max_sync(0xffffffffu, max(l0, l1));
        unsigned g = 0x3FFFu - ((lg >> 11) & 0x3FFFu);

        px = sxF[g]; py = syF[g]; pz = szF[g];
        if (rank == 0 && t == 0) {
            float* o = newxyz + ((size_t)b * M_ + it) * 3;
            o[0] = px; o[1] = py; o[2] = pz;
        }
    }

    asm volatile("barrier.cluster.arrive.aligned;" ::: "memory");
    asm volatile("barrier.cluster.wait.aligned;" ::: "memory");
}

// ------------------------------------------------------------------
// Ball query: one warp per centroid, 4 points/lane, early exit.
// ------------------------------------------------------------------
#define BQ_WARPS 8

__global__ void ballquery_kernel(const float* __restrict__ newxyz)
{
    const float R2 = (float)(0.8 * 0.8);
    int w = blockIdx.x * BQ_WARPS + (threadIdx.x >> 5);
    int lane = threadIdx.x & 31;
    if (w >= B_ * M_) return;
    int b = w / M_;

    float qx = newxyz[w * 3 + 0];
    float qy = newxyz[w * 3 + 1];
    float qz = newxyz[w * 3 + 2];
    const float* bx = g_soa[0][b];
    const float* by = g_soa[1][b];
    const float* bz = g_soa[2][b];
    int* out = g_ballidx + (size_t)w * NS_;

    int cnt = 0, firstidx = 0;
    for (int j0 = 0; j0 < N_ && cnt < NS_; j0 += 128) {
        float xv[4], yv[4], zv[4];
#pragma unroll
        for (int e = 0; e < 4; ++e) {
            int j = j0 + 32 * e + lane;
            xv[e] = bx[j]; yv[e] = by[j]; zv[e] = bz[j];
        }
        bool in[4];
#pragma unroll
        for (int e = 0; e < 4; ++e) {
            float dx = qx - xv[e], dy = qy - yv[e], dz = qz - zv[e];
            float d2 = __fadd_rn(__fadd_rn(__fmul_rn(dx, dx), __fmul_rn(dy, dy)),
                                 __fmul_rn(dz, dz));
            in[e] = d2 < R2;
        }
#pragma unroll
        for (int e = 0; e < 4; ++e) {
            unsigned bal = __ballot_sync(0xffffffffu, in[e]);
            if (bal) {
                if (cnt == 0) firstidx = j0 + 32 * e + __ffs(bal) - 1;
                int rnk = __popc(bal & ((1u << lane) - 1u));
                int pos = cnt + rnk;
                if (in[e] && pos < NS_) out[pos] = j0 + 32 * e + lane;
                cnt += __popc(bal);
            }
        }
    }
    int c2 = cnt < NS_ ? cnt : NS_;
    for (int pp = c2 + lane; pp < NS_; pp += 32) out[pp] = firstidx;
}

// ------------------------------------------------------------------
// Grouped MLP + max pool: 64 threads per centroid, f32x2 throughput.
// ------------------------------------------------------------------
#define MT 64

__global__ __launch_bounds__(MT)
void mlp_kernel(const float* __restrict__ feats,
                const float* __restrict__ newxyz,
                const float* __restrict__ w1, const float* __restrict__ b1,
                const float* __restrict__ w2, const float* __restrict__ b2,
                float* __restrict__ out_feats, float* __restrict__ out_bid)
{
    __shared__ uint32_t spin[67][32];
    __shared__ alignas(16) u64 sh1d[32][64];

    const int c = blockIdx.x;
    const int b = c >> 11;
    const int t = threadIdx.x;

    {
        const int s = t & 31, h = t >> 5;
        const int pt = g_ballidx[(size_t)c * NS_ + s];
        if (h == 0) {
            float qx = newxyz[c * 3 + 0];
            float qy = newxyz[c * 3 + 1];
            float qz = newxyz[c * 3 + 2];
            spin[0][s] = __float_as_uint(g_soa[0][b][pt] - qx);
            spin[1][s] = __float_as_uint(g_soa[1][b][pt] - qy);
            spin[2][s] = __float_as_uint(g_soa[2][b][pt] - qz);
        }
        const float4* fr = (const float4*)(feats + ((size_t)b * N_ + pt) * C_ + h * 32);
#pragma unroll
        for (int i = 0; i < 8; ++i) {
            float4 v = fr[i];
            int k = 3 + h * 32 + i * 4;
            spin[k + 0][s] = __float_as_uint(v.x);
            spin[k + 1][s] = __float_as_uint(v.y);
            spin[k + 2][s] = __float_as_uint(v.z);
            spin[k + 3][s] = __float_as_uint(v.w);
        }
    }
    __syncthreads();

    {
        u64 acc[16];
        float bl = b1[t];
        u64 bl2 = pack2(bl, bl);
#pragma unroll
        for (int p = 0; p < 16; ++p) acc[p] = bl2;

        const float* w1c = w1 + t;
#pragma unroll 2
        for (int k = 0; k < 67; ++k) {
            float wv = w1c[(size_t)k * 64];
            u64 w2k = pack2(wv, wv);
            const uint4* row = (const uint4*)&spin[k][0];
#pragma unroll
            for (int qq = 0; qq < 8; ++qq) {
                uint4 in4 = row[qq];
                u64 iA = pack2u(in4.x, in4.y);
                u64 iB = pack2u(in4.z, in4.w);
                acc[2 * qq]     = fmax2(iA, w2k, acc[2 * qq]);
                acc[2 * qq + 1] = fmax2(iB, w2k, acc[2 * qq + 1]);
            }
        }
#pragma unroll
        for (int p = 0; p < 16; ++p) {
            float a, bb; unpack2(a, bb, acc[p]);
            a = fmaxf(a, 0.0f); bb = fmaxf(bb, 0.0f);
            sh1d[2 * p][t]     = pack2(a, a);
            sh1d[2 * p + 1][t] = pack2(bb, bb);
        }
    }
    __syncthreads();

    {
        u64 w2r[64];
        const u64* w2p = (const u64*)w2;
#pragma unroll
        for (int k = 0; k < 64; ++k) w2r[k] = w2p[(size_t)k * 64 + t];

        float2 bb = ((const float2*)b2)[t];
        u64 binit = pack2(bb.x, bb.y);
        float m0 = 0.0f, m1 = 0.0f;

        for (int s = 0; s < 32; ++s) {
            u64 acc2 = binit;
            const ulonglong2* hr = (const ulonglong2*)&sh1d[s][0];
#pragma unroll
            for (int k2 = 0; k2 < 32; ++k2) {
                ulonglong2 hv = hr[k2];
                acc2 = fmax2(hv.x, w2r[2 * k2],     acc2);
                acc2 = fmax2(hv.y, w2r[2 * k2 + 1], acc2);
            }
            float a, bv; unpack2(a, bv, acc2);
            m0 = fmaxf(m0, fmaxf(a, 0.0f));
            m1 = fmaxf(m1, fmaxf(bv, 0.0f));
        }
        ((float2*)(out_feats + (size_t)c * 128))[t] = make_float2(m0, m1);
        if (t == 0) out_bid[c] = 0.0f;
    }
}

// ------------------------------------------------------------------
extern "C" void kernel_launch(void* const* d_in, const int* in_sizes, int n_in,
                              void* d_out, int out_size)
{
    const float* xyz   = (const float*)d_in[0];
    const float* feats = (const float*)d_in[1];
    const float* w1 = (const float*)d_in[3];
    const float* b1 = (const float*)d_in[4];
    const float* w2 = (const float*)d_in[5];
    const float* b2 = (const float*)d_in[6];

    float* out      = (float*)d_out;
    float* newxyz   = out;
    float* outfeats = out + B_ * M_ * 3;
    float* outbid   = outfeats + B_ * M_ * 128;

    cudaFuncSetAttribute(fps_kernel, cudaFuncAttributeMaxDynamicSharedMemorySize,
                         3 * N_ * 4);
    cudaFuncSetAttribute(fps_kernel, cudaFuncAttributeNonPortableClusterSizeAllowed, 1);

    cudaLaunchConfig_t cfg = {};
    cfg.gridDim = dim3(B_ * CS, 1, 1);
    cfg.blockDim = dim3(FT, 1, 1);
    cfg.dynamicSmemBytes = 3 * N_ * 4;
    cudaLaunchAttribute attrs[1];
    attrs[0].id = cudaLaunchAttributeClusterDimension;
    attrs[0].val.clusterDim.x = CS;
    attrs[0].val.clusterDim.y = 1;
    attrs[0].val.clusterDim.z = 1;
    cfg.attrs = attrs;
    cfg.numAttrs = 1;
    cudaLaunchKernelEx(&cfg, fps_kernel, xyz, newxyz);

    ballquery_kernel<<<(B_ * M_) / BQ_WARPS, BQ_WARPS * 32>>>(newxyz);
    mlp_kernel<<<B_ * M_, MT>>>(feats, newxyz, w1, b1, w2, b2,
                                outfeats, outbid);
}

// round 7
// speedup vs baseline: 1.0289x; 1.0289x over previous
#include <cuda_runtime.h>
#include <math.h>
#include <cstdint>

#define B_  4
#define N_  16384
#define C_  64
#define M_  2048
#define NS_ 32

// FPS cluster config (8-CTA cluster per batch — R5 topology)
#define CS    8
#define FT    256
#define NW    (FT / 32)           // 8 warps
#define NPC   (N_ / CS)           // 2048 points per CTA
#define PPT2  (NPC / FT)          // 8
#define PAIRS (PPT2 / 2)          // 4
#define NKEYS (CS * NW)           // 64 keys per exchange
#define XBYTES (NKEYS * 8)        // 512 bytes per buffer

typedef unsigned long long u64;

// scratch
__device__ int   g_ballidx[B_ * M_ * NS_];
__device__ float g_soa[3][B_][N_];

// ------------------------------------------------------------------
// PTX helpers
// ------------------------------------------------------------------
__device__ __forceinline__ uint32_t smem_u32(const void* p) {
    uint32_t a;
    asm("{ .reg .u64 t; cvta.to.shared.u64 t, %1; cvt.u32.u64 %0, t; }"
        : "=r"(a) : "l"(p));
    return a;
}
__device__ __forceinline__ uint32_t ctarank() {
    uint32_t r; asm("mov.u32 %0, %%cluster_ctarank;" : "=r"(r)); return r;
}
__device__ __forceinline__ uint32_t mapa_u32(uint32_t addr, uint32_t rank) {
    uint32_t r;
    asm("mapa.shared::cluster.u32 %0, %1, %2;" : "=r"(r) : "r"(addr), "r"(rank));
    return r;
}
__device__ __forceinline__ void st_rel64(uint32_t raddr, u64 v) {
    asm volatile("st.relaxed.cluster.shared::cluster.b64 [%0], %1;"
                 :: "r"(raddr), "l"(v) : "memory");
}
__device__ __forceinline__ void ld_vol_v2(u64& k0, u64& k1, uint32_t addr) {
    asm volatile("ld.volatile.shared.v2.u64 {%0,%1}, [%2];"
                 : "=l"(k0), "=l"(k1) : "r"(addr) : "memory");
}
__device__ __forceinline__ u64 pack2(float lo, float hi) {
    u64 r;
    asm("mov.b64 %0, {%1,%2};" : "=l"(r)
        : "r"(__float_as_uint(lo)), "r"(__float_as_uint(hi)));
    return r;
}
__device__ __forceinline__ u64 pack2u(uint32_t lo, uint32_t hi) {
    u64 r;
    asm("mov.b64 %0, {%1,%2};" : "=l"(r) : "r"(lo), "r"(hi));
    return r;
}
__device__ __forceinline__ void unpack2(float& lo, float& hi, u64 v) {
    uint32_t a, b;
    asm("mov.b64 {%0,%1}, %2;" : "=r"(a), "=r"(b) : "l"(v));
    lo = __uint_as_float(a); hi = __uint_as_float(b);
}
__device__ __forceinline__ u64 addx2(u64 a, u64 b) {
    u64 r; asm("add.rn.f32x2 %0, %1, %2;" : "=l"(r) : "l"(a), "l"(b)); return r;
}
__device__ __forceinline__ u64 mulx2(u64 a, u64 b) {
    u64 r; asm("mul.rn.f32x2 %0, %1, %2;" : "=l"(r) : "l"(a), "l"(b)); return r;
}
__device__ __forceinline__ u64 fmax2(u64 a, u64 b, u64 c) {
    u64 r; asm("fma.rn.f32x2 %0, %1, %2, %3;" : "=l"(r) : "l"(a), "l"(b), "l"(c));
    return r;
}

// ------------------------------------------------------------------
// FPS: one 8-CTA cluster per batch. Full xyz mirror in dynamic smem;
// per-warp winners shipped via relaxed DSMEM stores with iteration
// tag embedded (no mbarrier); receiver polls its 64 slots with
// volatile v2 loads, then two-stage REDUX lexicographic argmax.
// Key: [63:32]=dist bits, [24:11]=0x3FFF-idx, [10:0]=iteration tag.
// ------------------------------------------------------------------
__global__ __launch_bounds__(FT, 1) __cluster_dims__(CS, 1, 1)
void fps_kernel(const float* __restrict__ xyz, float* __restrict__ newxyz)
{
    extern __shared__ float mir[];         // [3][N_] coordinate mirror
    float* sxF = mir;
    float* syF = mir + N_;
    float* szF = mir + 2 * N_;

    __shared__ alignas(16) u64 cand[2][NKEYS];

    const uint32_t rank = ctarank();
    const int b = blockIdx.x / CS;
    const int t = threadIdx.x;
    const int wid = t >> 5;
    const int lane = t & 31;
    const uint32_t candB = smem_u32(&cand[0][0]);

    // zero both candidate buffers (tag 0 never polled; it starts at 1)
    for (int i = t; i < 2 * NKEYS; i += FT) cand[0][i] = 0ull;

    // load full batch xyz into mirror (SoA)
    const float* base = xyz + (size_t)b * N_ * 3;
    for (int i = t; i < N_; i += FT) {
        sxF[i] = base[3 * i + 0];
        syF[i] = base[3 * i + 1];
        szF[i] = base[3 * i + 2];
    }
    __syncthreads();

    // dump this CTA's chunk to the global SoA for ballquery/mlp
    const int goff = (int)rank * NPC;
    for (int i = goff + t; i < goff + NPC; i += FT) {
        g_soa[0][b][i] = sxF[i];
        g_soa[1][b][i] = syF[i];
        g_soa[2][b][i] = szF[i];
    }

    asm volatile("barrier.cluster.arrive.aligned;" ::: "memory");
    asm volatile("barrier.cluster.wait.aligned;" ::: "memory");

    // own points packed in registers
    u64 qx2[PAIRS], qy2[PAIRS], qz2[PAIRS];
    float qd[PPT2];
#pragma unroll
    for (int j = 0; j < PAIRS; ++j) {
        int nA = goff + (2 * j) * FT + t, nB = goff + (2 * j + 1) * FT + t;
        qx2[j] = pack2(sxF[nA], sxF[nB]);
        qy2[j] = pack2(syF[nA], syF[nB]);
        qz2[j] = pack2(szF[nA], szF[nB]);
        qd[2 * j] = 1e10f; qd[2 * j + 1] = 1e10f;
    }

    // precomputed remote slot addresses (lane < CS targets CTA 'lane')
    const uint32_t myslotoff = (uint32_t)(rank * NW + wid) * 8;
    uint32_t rc0 = 0, rc1 = 0;
    if (lane < CS) {
        rc0 = mapa_u32(candB + myslotoff,                    (uint32_t)lane);
        rc1 = mapa_u32(candB + (uint32_t)XBYTES + myslotoff, (uint32_t)lane);
    }
    const uint32_t pollA = candB + (uint32_t)lane * 16;

    float px = sxF[0], py = syF[0], pz = szF[0];
    if (rank == 0 && t == 0) {
        float* o = newxyz + (size_t)b * M_ * 3;
        o[0] = px; o[1] = py; o[2] = pz;
    }

    for (int it = 1; it < M_; ++it) {
        const uint32_t s = (uint32_t)it & 1u;

        u64 npx2 = pack2(-px, -px);
        u64 npy2 = pack2(-py, -py);
        u64 npz2 = pack2(-pz, -pz);

        float n[PPT2];
#pragma unroll
        for (int j = 0; j < PAIRS; ++j) {
            u64 dx2 = addx2(qx2[j], npx2);
            u64 dy2 = addx2(qy2[j], npy2);
            u64 dz2 = addx2(qz2[j], npz2);
            u64 ss = addx2(addx2(mulx2(dx2, dx2), mulx2(dy2, dy2)),
                           mulx2(dz2, dz2));
            float d0, d1; unpack2(d0, d1, ss);
            n[2 * j]     = fminf(qd[2 * j], d0);     qd[2 * j]     = n[2 * j];
            n[2 * j + 1] = fminf(qd[2 * j + 1], d1); qd[2 * j + 1] = n[2 * j + 1];
        }

        // local value-max tree + first-matching-slot (ascending index)
        float a0 = fmaxf(n[0], n[1]), a1 = fmaxf(n[2], n[3]);
        float a2 = fmaxf(n[4], n[5]), a3 = fmaxf(n[6], n[7]);
        float vmax = fmaxf(fmaxf(a0, a1), fmaxf(a2, a3));
        int c0 = (n[0] == vmax) ? 0 : 99, c1 = (n[1] == vmax) ? 1 : 99;
        int c2 = (n[2] == vmax) ? 2 : 99, c3 = (n[3] == vmax) ? 3 : 99;
        int c4 = (n[4] == vmax) ? 4 : 99, c5 = (n[5] == vmax) ? 5 : 99;
        int c6 = (n[6] == vmax) ? 6 : 99, c7 = (n[7] == vmax) ? 7 : 99;
        int bk = min(min(min(c0, c1), min(c2, c3)),
                     min(min(c4, c5), min(c6, c7)));

        // warp-level exact argmax (d>=0 -> float bits monotonic as uint)
        unsigned vb = __float_as_uint(vmax);
        unsigned vmaxW = __reduce_max_sync(0xffffffffu, vb);
        unsigned gidx = (unsigned)goff + (unsigned)bk * FT + (unsigned)t;
        unsigned ic = (vb == vmaxW) ? gidx : 0xffffffffu;
        unsigned imin = __reduce_min_sync(0xffffffffu, ic);
        u64 key = ((u64)vmaxW << 32)
                | ((u64)(0x3FFFu - imin) << 11)
                | (u64)(unsigned)it;

        // ship this warp's winner to all CTAs (lanes 0..CS-1)
        if (lane < CS)
            st_rel64(s ? rc1 : rc0, key);

        // poll own 2 slots until all 64 keys carry this iteration's tag
        const uint32_t pa = pollA + s * (uint32_t)XBYTES;
        u64 k0, k1;
        for (;;) {
            ld_vol_v2(k0, k1, pa);
            bool ok = (((unsigned)k0 & 0x7FFu) == (unsigned)it) &&
                      (((unsigned)k1 & 0x7FFu) == (unsigned)it);
            if (__all_sync(0xffffffffu, ok)) break;
        }

        // two-stage REDUX lexicographic max over 64 keys
        unsigned h0 = (unsigned)(k0 >> 32), h1 = (unsigned)(k1 >> 32);
        unsigned vg = __reduce_max_sync(0xffffffffu, max(h0, h1));
        unsigned l0 = (h0 == vg) ? (unsigned)k0 : 0u;
        unsigned l1 = (h1 == vg) ? (unsigned)k1 : 0u;
        unsigned lg = __reduce_max_sync(0xffffffffu, max(l0, l1));
        unsigned g = 0x3FFFu - ((lg >> 11) & 0x3FFFu);

        px = sxF[g]; py = syF[g]; pz = szF[g];
        if (rank == 0 && t == 0) {
            float* o = newxyz + ((size_t)b * M_ + it) * 3;
            o[0] = px; o[1] = py; o[2] = pz;
        }
    }

    asm volatile("barrier.cluster.arrive.aligned;" ::: "memory");
    asm volatile("barrier.cluster.wait.aligned;" ::: "memory");
}

// ------------------------------------------------------------------
// Ball query: one warp per centroid, 4 points/lane, early exit.
// ------------------------------------------------------------------
#define BQ_WARPS 8

__global__ void ballquery_kernel(const float* __restrict__ newxyz)
{
    const float R2 = (float)(0.8 * 0.8);
    int w = blockIdx.x * BQ_WARPS + (threadIdx.x >> 5);
    int lane = threadIdx.x & 31;
    if (w >= B_ * M_) return;
    int b = w / M_;

    float qx = newxyz[w * 3 + 0];
    float qy = newxyz[w * 3 + 1];
    float qz = newxyz[w * 3 + 2];
    const float* bx = g_soa[0][b];
    const float* by = g_soa[1][b];
    const float* bz = g_soa[2][b];
    int* out = g_ballidx + (size_t)w * NS_;

    int cnt = 0, firstidx = 0;
    for (int j0 = 0; j0 < N_ && cnt < NS_; j0 += 128) {
        float xv[4], yv[4], zv[4];
#pragma unroll
        for (int e = 0; e < 4; ++e) {
            int j = j0 + 32 * e + lane;
            xv[e] = bx[j]; yv[e] = by[j]; zv[e] = bz[j];
        }
        bool in[4];
#pragma unroll
        for (int e = 0; e < 4; ++e) {
            float dx = qx - xv[e], dy = qy - yv[e], dz = qz - zv[e];
            float d2 = __fadd_rn(__fadd_rn(__fmul_rn(dx, dx), __fmul_rn(dy, dy)),
                                 __fmul_rn(dz, dz));
            in[e] = d2 < R2;
        }
#pragma unroll
        for (int e = 0; e < 4; ++e) {
            unsigned bal = __ballot_sync(0xffffffffu, in[e]);
            if (bal) {
                if (cnt == 0) firstidx = j0 + 32 * e + __ffs(bal) - 1;
                int rnk = __popc(bal & ((1u << lane) - 1u));
                int pos = cnt + rnk;
                if (in[e] && pos < NS_) out[pos] = j0 + 32 * e + lane;
                cnt += __popc(bal);
            }
        }
    }
    int c2 = cnt < NS_ ? cnt : NS_;
    for (int pp = c2 + lane; pp < NS_; pp += 32) out[pp] = firstidx;
}

// ------------------------------------------------------------------
// Grouped MLP + max pool: 64 threads per centroid, f32x2 throughput.
// ------------------------------------------------------------------
#define MT 64

__global__ __launch_bounds__(MT)
void mlp_kernel(const float* __restrict__ feats,
                const float* __restrict__ newxyz,
                const float* __restrict__ w1, const float* __restrict__ b1,
                const float* __restrict__ w2, const float* __restrict__ b2,
                float* __restrict__ out_feats, float* __restrict__ out_bid)
{
    __shared__ uint32_t spin[67][32];
    __shared__ alignas(16) u64 sh1d[32][64];

    const int c = blockIdx.x;
    const int b = c >> 11;
    const int t = threadIdx.x;

    {
        const int s = t & 31, h = t >> 5;
        const int pt = g_ballidx[(size_t)c * NS_ + s];
        if (h == 0) {
            float qx = newxyz[c * 3 + 0];
            float qy = newxyz[c * 3 + 1];
            float qz = newxyz[c * 3 + 2];
            spin[0][s] = __float_as_uint(g_soa[0][b][pt] - qx);
            spin[1][s] = __float_as_uint(g_soa[1][b][pt] - qy);
            spin[2][s] = __float_as_uint(g_soa[2][b][pt] - qz);
        }
        const float4* fr = (const float4*)(feats + ((size_t)b * N_ + pt) * C_ + h * 32);
#pragma unroll
        for (int i = 0; i < 8; ++i) {
            float4 v = fr[i];
            int k = 3 + h * 32 + i * 4;
            spin[k + 0][s] = __float_as_uint(v.x);
            spin[k + 1][s] = __float_as_uint(v.y);
            spin[k + 2][s] = __float_as_uint(v.z);
            spin[k + 3][s] = __float_as_uint(v.w);
        }
    }
    __syncthreads();

    {
        u64 acc[16];
        float bl = b1[t];
        u64 bl2 = pack2(bl, bl);
#pragma unroll
        for (int p = 0; p < 16; ++p) acc[p] = bl2;

        const float* w1c = w1 + t;
#pragma unroll 2
        for (int k = 0; k < 67; ++k) {
            float wv = w1c[(size_t)k * 64];
            u64 w2k = pack2(wv, wv);
            const uint4* row = (const uint4*)&spin[k][0];
#pragma unroll
            for (int qq = 0; qq < 8; ++qq) {
                uint4 in4 = row[qq];
                u64 iA = pack2u(in4.x, in4.y);
                u64 iB = pack2u(in4.z, in4.w);
                acc[2 * qq]     = fmax2(iA, w2k, acc[2 * qq]);
                acc[2 * qq + 1] = fmax2(iB, w2k, acc[2 * qq + 1]);
            }
        }
#pragma unroll
        for (int p = 0; p < 16; ++p) {
            float a, bb; unpack2(a, bb, acc[p]);
            a = fmaxf(a, 0.0f); bb = fmaxf(bb, 0.0f);
            sh1d[2 * p][t]     = pack2(a, a);
            sh1d[2 * p + 1][t] = pack2(bb, bb);
        }
    }
    __syncthreads();

    {
        u64 w2r[64];
        const u64* w2p = (const u64*)w2;
#pragma unroll
        for (int k = 0; k < 64; ++k) w2r[k] = w2p[(size_t)k * 64 + t];

        float2 bb = ((const float2*)b2)[t];
        u64 binit = pack2(bb.x, bb.y);
        float m0 = 0.0f, m1 = 0.0f;

        for (int s = 0; s < 32; ++s) {
            u64 acc2 = binit;
            const ulonglong2* hr = (const ulonglong2*)&sh1d[s][0];
#pragma unroll
            for (int k2 = 0; k2 < 32; ++k2) {
                ulonglong2 hv = hr[k2];
                acc2 = fmax2(hv.x, w2r[2 * k2],     acc2);
                acc2 = fmax2(hv.y, w2r[2 * k2 + 1], acc2);
            }
            float a, bv; unpack2(a, bv, acc2);
            m0 = fmaxf(m0, fmaxf(a, 0.0f));
            m1 = fmaxf(m1, fmaxf(bv, 0.0f));
        }
        ((float2*)(out_feats + (size_t)c * 128))[t] = make_float2(m0, m1);
        if (t == 0) out_bid[c] = 0.0f;
    }
}

// ------------------------------------------------------------------
extern "C" void kernel_launch(void* const* d_in, const int* in_sizes, int n_in,
                              void* d_out, int out_size)
{
    const float* xyz   = (const float*)d_in[0];
    const float* feats = (const float*)d_in[1];
    const float* w1 = (const float*)d_in[3];
    const float* b1 = (const float*)d_in[4];
    const float* w2 = (const float*)d_in[5];
    const float* b2 = (const float*)d_in[6];

    float* out      = (float*)d_out;
    float* newxyz   = out;
    float* outfeats = out + B_ * M_ * 3;
    float* outbid   = outfeats + B_ * M_ * 128;

    cudaFuncSetAttribute(fps_kernel, cudaFuncAttributeMaxDynamicSharedMemorySize,
                         3 * N_ * 4);

    fps_kernel<<<B_ * CS, FT, 3 * N_ * 4>>>(xyz, newxyz);
    ballquery_kernel<<<(B_ * M_) / BQ_WARPS, BQ_WARPS * 32>>>(newxyz);
    mlp_kernel<<<B_ * M_, MT>>>(feats, newxyz, w1, b1, w2, b2,
                                outfeats, outbid);
}